// round 6
// baseline (speedup 1.0000x reference)
#include <cuda_runtime.h>
#include <cstdint>

#define BB 32
#define CC 512
#define HWP 784
#define MM 200
#define NCC 50
#define NMM 4
#define KK 5

#define MT 32
#define PT 16            // pixels per block tile (4 quads)
#define CT 4             // channels per pipeline stage
#define NSTEP (CC / CT)  // 128

// smem layout in float4 (16B) units. Per channel per operand: 32 rows with
// row stride 5 f4 (4 data + 1 pad) -> conflict-free LDS.128 reads (phase
// quads (20*mg+5j+q) mod 8 distinct) and conflict-free cp.async writes.
#define CHF4 160                  // 32 * 5
#define STF4 (CT * CHF4)          // 640 per operand
#define BUFF4 (2 * STF4)          // 1280 (x + m)
#define FLSB 160                  // fls per-b stride (32 m * 5)
#define SDENF4 5120               // sden after fls overlay (32*160)
#define ARENAF4 (SDENF4 + 128)    // 5248 f4 = 83968 B

typedef unsigned long long ull;

__device__ float g_bg[BB * KK * HWP];
__device__ float g_pm[BB * MM * KK];

__device__ __forceinline__ unsigned su32(const void* p) {
    return (unsigned)__cvta_generic_to_shared(p);
}

// ---------------------------------------------------------------------------
// bg (+ fused clutter normalization + g_pm zeroing)
// ---------------------------------------------------------------------------
__global__ void __launch_bounds__(256) bg_kernel(const float* __restrict__ x,
                                                 const float* __restrict__ clutter) {
    __shared__ float cls[KK * CC];
    __shared__ float part[16][16 * KK];
    __shared__ float red[8];
    __shared__ float rtot;

    const int tid = threadIdx.x;
    const int b = blockIdx.y;
    const int px0 = blockIdx.x * 16;
    const int lane = tid & 31, w = tid >> 5;

    const int zi = (blockIdx.y * 49 + blockIdx.x) * 256 + tid;
    if (zi < BB * MM * KK) g_pm[zi] = 0.0f;

    for (int k = 0; k < KK; ++k) {
        float v0 = fminf(fmaxf(clutter[k * CC + tid], 0.f), 1.f);
        float v1 = fminf(fmaxf(clutter[k * CC + 256 + tid], 0.f), 1.f);
        float s = v0 + v1;
        #pragma unroll
        for (int o = 16; o > 0; o >>= 1) s += __shfl_xor_sync(0xffffffffu, s, o);
        if (lane == 0) red[w] = s;
        __syncthreads();
        if (tid == 0) {
            float r = 0.f;
            #pragma unroll
            for (int q = 0; q < 8; ++q) r += red[q];
            rtot = fmaxf(r, 1e-12f);
        }
        __syncthreads();
        const float inv = __frcp_rn(rtot);
        cls[k * CC + tid] = v0 * inv;
        cls[k * CC + 256 + tid] = v1 * inv;
        __syncthreads();
    }

    const int px = tid & 15;
    const int cg = tid >> 4;
    float a0 = 0.f, a1 = 0.f, a2 = 0.f, a3 = 0.f, a4 = 0.f;
    const float* xb = x + ((size_t)b * CC + cg * 32) * HWP + px0 + px;
    #pragma unroll 4
    for (int ci = 0; ci < 32; ++ci) {
        const int c = cg * 32 + ci;
        const float xv = xb[(size_t)ci * HWP];
        a0 += xv * cls[0 * CC + c];
        a1 += xv * cls[1 * CC + c];
        a2 += xv * cls[2 * CC + c];
        a3 += xv * cls[3 * CC + c];
        a4 += xv * cls[4 * CC + c];
    }
    part[cg][px * KK + 0] = a0;
    part[cg][px * KK + 1] = a1;
    part[cg][px * KK + 2] = a2;
    part[cg][px * KK + 3] = a3;
    part[cg][px * KK + 4] = a4;
    __syncthreads();

    if (tid < 16 * KK) {
        float s = 0.f;
        #pragma unroll
        for (int g = 0; g < 16; ++g) s += part[g][tid];
        const int p = tid / KK, k = tid % KK;
        g_bg[((size_t)b * KK + k) * HWP + px0 + p] = __logf(s * 0.3f + 1e-10f);
    }
}

// ---------------------------------------------------------------------------
// fg: block 128 = 4bg(warps) x 8mg x 4pc2 ; thread tile 8b x 4m x 4px (quad).
// All smem traffic via LDS.128; 13 LDS / 66 FMA-pipe ops per thread-channel.
// ---------------------------------------------------------------------------
__global__ void __launch_bounds__(128, 2) fg_kernel(const float* __restrict__ x,
                                                    const float* __restrict__ mix) {
    extern __shared__ float4 arena[];
    float4* sden = arena + SDENF4;       // [mrow(32)][q(4)] float4
    float4* fls  = arena;                // epilogue overlay [b][m*5 + q]

    const int tid   = threadIdx.x;
    const int mtile = blockIdx.x;        // 7
    const int ptile = blockIdx.y;        // 49
    const int mbase = mtile * MT;
    const int px0   = ptile * PT;

    // ---- loader mapping: lrow = tid&31, lc = tid>>5 (channel within stage)
    const int lrow = tid & 31;
    const int lc   = tid >> 5;
    const int mrow_ld = (mbase + lrow < MM) ? mbase + lrow : MM - 1;
    const float* xsrc = x   + ((size_t)lrow    * CC + lc) * HWP + px0;
    const float* msrc = mix + ((size_t)mrow_ld * CC + lc) * HWP + px0;
    const int xdst_f4 = lc * CHF4 + 5 * lrow;
    const unsigned sm_b = su32(arena);

    // ---- compute mapping
    const int pc2 = tid & 3;             // pixel quad
    const int mg  = (tid >> 2) & 7;      // 8 m-groups x 4
    const int bg  = tid >> 5;            // warp id, 4 b-groups x 8
    int xidx[8], midx[4];
    #pragma unroll
    for (int i = 0; i < 8; ++i) xidx[i] = 5 * (bg * 8 + i) + pc2;
    #pragma unroll
    for (int j = 0; j < 4; ++j) midx[j] = STF4 + 5 * (mg * 4 + j) + pc2;
    const int didx = STF4 + 5 * (mg * 4 + bg) + pc2;

    ulonglong2 acc[8][4];
    ulonglong2 dden;
    dden.x = 0ull; dden.y = 0ull;
    #pragma unroll
    for (int i = 0; i < 8; ++i)
        #pragma unroll
        for (int j = 0; j < 4; ++j) { acc[i][j].x = 0ull; acc[i][j].y = 0ull; }

#define LOAD_STAGE(buf, s)                                                        \
    {                                                                             \
        const size_t go = (size_t)(s) * CT * HWP;                                 \
        _Pragma("unroll")                                                         \
        for (int q = 0; q < 4; ++q) {                                             \
            unsigned dx = sm_b + (unsigned)(((buf) * BUFF4 + xdst_f4 + q) * 16);  \
            unsigned dm = dx + (unsigned)(STF4 * 16);                             \
            asm volatile("cp.async.cg.shared.global [%0], [%1], 16;"              \
                         ::"r"(dx), "l"(xsrc + go + 4 * q));                      \
            asm volatile("cp.async.cg.shared.global [%0], [%1], 16;"              \
                         ::"r"(dm), "l"(msrc + go + 4 * q));                      \
        }                                                                         \
        asm volatile("cp.async.commit_group;");                                   \
    }

#define STEP(cur, nxt, s)                                                         \
    {                                                                             \
        asm volatile("cp.async.wait_group 1;");                                   \
        __syncthreads();                                                          \
        {                                                                         \
            const int ns = ((s) + 2 < NSTEP) ? (s) + 2 : NSTEP - 1;               \
            LOAD_STAGE(nxt, ns);                                                  \
        }                                                                         \
        {                                                                         \
            const ulonglong2* base =                                              \
                (const ulonglong2*)(arena + (cur) * BUFF4);                       \
            _Pragma("unroll")                                                     \
            for (int c = 0; c < CT; ++c) {                                        \
                const ulonglong2* cb = base + c * CHF4;                           \
                ulonglong2 xr[8];                                                 \
                _Pragma("unroll")                                                 \
                for (int i = 0; i < 8; ++i) xr[i] = cb[xidx[i]];                  \
                const ulonglong2 dm = cb[didx];                                   \
                asm("add.rn.f32x2 %0, %0, %1;" : "+l"(dden.x) : "l"(dm.x));       \
                asm("add.rn.f32x2 %0, %0, %1;" : "+l"(dden.y) : "l"(dm.y));       \
                _Pragma("unroll")                                                 \
                for (int j = 0; j < 4; ++j) {                                     \
                    const ulonglong2 mr = cb[midx[j]];                            \
                    _Pragma("unroll")                                             \
                    for (int i = 0; i < 8; ++i) {                                 \
                        asm("fma.rn.f32x2 %0, %1, %2, %0;"                        \
                            : "+l"(acc[i][j].x) : "l"(xr[i].x), "l"(mr.x));       \
                        asm("fma.rn.f32x2 %0, %1, %2, %0;"                        \
                            : "+l"(acc[i][j].y) : "l"(xr[i].y), "l"(mr.y));       \
                    }                                                             \
                }                                                                 \
            }                                                                     \
        }                                                                         \
    }

    // ---- prologue
    LOAD_STAGE(0, 0)
    LOAD_STAGE(1, 1)

    // ---- main loop: 128 steps = 42*3 + 2
    for (int it = 0; it < 42; ++it) {
        const int s = it * 3;
        STEP(0, 2, s)
        STEP(1, 0, s + 1)
        STEP(2, 1, s + 2)
    }
    STEP(0, 2, 126)
    STEP(1, 0, 127)

    asm volatile("cp.async.wait_group 0;");
    __syncthreads();

    // ---- denominators -> sden: thread (bg,mg,pc2) owns m-row mg*4+bg, quad pc2
    sden[(mg * 4 + bg) * 4 + pc2] = *(const float4*)&dden;
    __syncthreads();

    // ---- fl = log(acc/den * 0.7 + 1e-10) -> fls overlay (stride-5 m rows)
    #pragma unroll
    for (int j = 0; j < 4; ++j) {
        const int mrow = mg * 4 + j;
        const float4 d = sden[mrow * 4 + pc2];
        float4 iv;
        iv.x = __fdividef(0.7f, fmaxf(d.x, 1e-12f));
        iv.y = __fdividef(0.7f, fmaxf(d.y, 1e-12f));
        iv.z = __fdividef(0.7f, fmaxf(d.z, 1e-12f));
        iv.w = __fdividef(0.7f, fmaxf(d.w, 1e-12f));
        #pragma unroll
        for (int i = 0; i < 8; ++i) {
            const int b = bg * 8 + i;
            const float4 a = *(const float4*)&acc[i][j];
            float4 f;
            f.x = __logf(a.x * iv.x + 1e-10f);
            f.y = __logf(a.y * iv.y + 1e-10f);
            f.z = __logf(a.z * iv.z + 1e-10f);
            f.w = __logf(a.w * iv.w + 1e-10f);
            fls[b * FLSB + mrow * 5 + pc2] = f;
        }
    }
    __syncthreads();

    // ---- occlusion-max + pixel reduction + global accumulate
    #pragma unroll
    for (int rep = 0; rep < 8; ++rep) {
        const int cell = tid + rep * 128;      // 0..1023
        const int b = cell >> 5;
        const int ml = cell & 31;
        const int m_g = mbase + ml;
        float4 fv[4];
        #pragma unroll
        for (int q = 0; q < 4; ++q) fv[q] = fls[b * FLSB + ml * 5 + q];
        float sk[KK];
        #pragma unroll
        for (int k = 0; k < KK; ++k) {
            float s = 0.f;
            const float* bgp = g_bg + ((size_t)b * KK + k) * HWP + px0;
            #pragma unroll
            for (int q = 0; q < 4; ++q) {
                const float4 bv = *(const float4*)(bgp + q * 4);
                s += fmaxf(fv[q].x, bv.x) + fmaxf(fv[q].y, bv.y) +
                     fmaxf(fv[q].z, bv.z) + fmaxf(fv[q].w, bv.w);
            }
            sk[k] = s;
        }
        if (m_g < MM) {
            float* pmp = g_pm + ((size_t)b * MM + m_g) * KK;
            #pragma unroll
            for (int k = 0; k < KK; ++k) atomicAdd(&pmp[k], sk[k]);
        }
    }
#undef STEP
#undef LOAD_STAGE
}

// ---------------------------------------------------------------------------
__global__ void final_kernel(float* __restrict__ out) {
    const int idx = blockIdx.x * 256 + threadIdx.x;
    if (idx >= BB * NCC) return;
    const int b = idx / NCC, nc = idx % NCC;
    const float* p = g_pm + ((size_t)b * MM + nc * NMM) * KK;
    float m = -3.402823466e+38f;
    #pragma unroll
    for (int t = 0; t < NMM * KK; ++t) m = fmaxf(m, p[t]);
    out[idx] = m;
}

// ---------------------------------------------------------------------------
extern "C" void kernel_launch(void* const* d_in, const int* in_sizes, int n_in,
                              void* d_out, int out_size) {
    const float* x       = (const float*)d_in[0];
    const float* mix     = (const float*)d_in[1];
    const float* clutter = (const float*)d_in[2];
    float* out = (float*)d_out;

    const int fg_smem = ARENAF4 * 16;    // 83968 B
    cudaFuncSetAttribute(fg_kernel, cudaFuncAttributeMaxDynamicSharedMemorySize,
                         fg_smem);

    bg_kernel<<<dim3(49, BB), 256>>>(x, clutter);
    fg_kernel<<<dim3((MM + MT - 1) / MT, HWP / PT), 128, fg_smem>>>(x, mix);
    final_kernel<<<(BB * NCC + 255) / 256, 256>>>(out);
}

// round 7
// speedup vs baseline: 1.0009x; 1.0009x over previous
#include <cuda_runtime.h>
#include <cstdint>

#define BB 32
#define CC 512
#define HWP 784
#define MM 200
#define NCC 50
#define NMM 4
#define KK 5

#define MT 32
#define PT 16            // pixels per block tile (8 pairs)
#define CT 4             // channels per pipeline stage
#define NSTEP (CC / CT)  // 128

// smem layout (float2 units), identical to the validated R5 layout:
// per channel per operand: 4 groups of 8 rows, group stride 72 f2
// (8 rows x 8 f2 + 8 f2 pad); within each row the four 16B chunks are
// XOR-swizzled by (row&3).
#define CHF2 288                   // 4 * 72
#define STAGEF2 (CT * CHF2)        // 1152
#define BUFF2 (2 * STAGEF2)        // x + m = 2304
#define SDENF2 8192                // sden after the 64KB fls overlay
#define ARENAF2 (SDENF2 + 256)     // 8448 f2 = 67584 B

typedef unsigned long long ull;

__device__ float g_bg[BB * KK * HWP];
__device__ float g_pm[BB * MM * KK];

__device__ __forceinline__ unsigned su32(const void* p) {
    return (unsigned)__cvta_generic_to_shared(p);
}

// ---------------------------------------------------------------------------
// bg (+ fused clutter normalization + g_pm zeroing)
// ---------------------------------------------------------------------------
__global__ void __launch_bounds__(256) bg_kernel(const float* __restrict__ x,
                                                 const float* __restrict__ clutter) {
    __shared__ float cls[KK * CC];
    __shared__ float part[16][16 * KK];
    __shared__ float red[8];
    __shared__ float rtot;

    const int tid = threadIdx.x;
    const int b = blockIdx.y;
    const int px0 = blockIdx.x * 16;
    const int lane = tid & 31, w = tid >> 5;

    const int zi = (blockIdx.y * 49 + blockIdx.x) * 256 + tid;
    if (zi < BB * MM * KK) g_pm[zi] = 0.0f;

    for (int k = 0; k < KK; ++k) {
        float v0 = fminf(fmaxf(clutter[k * CC + tid], 0.f), 1.f);
        float v1 = fminf(fmaxf(clutter[k * CC + 256 + tid], 0.f), 1.f);
        float s = v0 + v1;
        #pragma unroll
        for (int o = 16; o > 0; o >>= 1) s += __shfl_xor_sync(0xffffffffu, s, o);
        if (lane == 0) red[w] = s;
        __syncthreads();
        if (tid == 0) {
            float r = 0.f;
            #pragma unroll
            for (int q = 0; q < 8; ++q) r += red[q];
            rtot = fmaxf(r, 1e-12f);
        }
        __syncthreads();
        const float inv = __frcp_rn(rtot);
        cls[k * CC + tid] = v0 * inv;
        cls[k * CC + 256 + tid] = v1 * inv;
        __syncthreads();
    }

    const int px = tid & 15;
    const int cg = tid >> 4;
    float a0 = 0.f, a1 = 0.f, a2 = 0.f, a3 = 0.f, a4 = 0.f;
    const float* xb = x + ((size_t)b * CC + cg * 32) * HWP + px0 + px;
    #pragma unroll 4
    for (int ci = 0; ci < 32; ++ci) {
        const int c = cg * 32 + ci;
        const float xv = xb[(size_t)ci * HWP];
        a0 += xv * cls[0 * CC + c];
        a1 += xv * cls[1 * CC + c];
        a2 += xv * cls[2 * CC + c];
        a3 += xv * cls[3 * CC + c];
        a4 += xv * cls[4 * CC + c];
    }
    part[cg][px * KK + 0] = a0;
    part[cg][px * KK + 1] = a1;
    part[cg][px * KK + 2] = a2;
    part[cg][px * KK + 3] = a3;
    part[cg][px * KK + 4] = a4;
    __syncthreads();

    if (tid < 16 * KK) {
        float s = 0.f;
        #pragma unroll
        for (int g = 0; g < 16; ++g) s += part[g][tid];
        const int p = tid / KK, k = tid % KK;
        g_bg[((size_t)b * KK + k) * HWP + px0 + p] = __logf(s * 0.3f + 1e-10f);
    }
}

// ---------------------------------------------------------------------------
// fg: block 256 = 8 warps (wid = mgh*4 + bg) x lanes (mg(4) x pc(8)).
// Thread tile 8b x 4m x 2px -> acc 64 regs, 4 warps/SMSP at 2 CTA/SM.
// Same smem layout / swizzle / pipeline as the validated R5 kernel.
// ---------------------------------------------------------------------------
__global__ void __launch_bounds__(256, 2) fg_kernel(const float* __restrict__ x,
                                                    const float* __restrict__ mix) {
    extern __shared__ float2 arena[];
    float2* sden = arena + SDENF2;       // [mrow(32)][pc(8)] float2
    float2* fls  = arena;                // epilogue overlay [b][mrow][pc]

    const int tid   = threadIdx.x;
    const int mtile = blockIdx.x;        // 7
    const int ptile = blockIdx.y;        // 49
    const int mbase = mtile * MT;
    const int px0   = ptile * PT;

    // ---- loader mapping: 256 threads, half x / half m; each (row, ch)
    const int lrow = tid & 31;
    const int lc   = (tid >> 5) & 3;
    const bool isx = tid < 128;
    const int mrow_ld = (mbase + lrow < MM) ? mbase + lrow : MM - 1;
    const float* lsrc = isx
        ? x   + ((size_t)lrow    * CC + lc) * HWP + px0
        : mix + ((size_t)mrow_ld * CC + lc) * HWP + px0;
    const int lbase = isx ? 0 : STAGEF2;
    const int rowb_f2 = lbase + lc * CHF2 + 72 * (lrow >> 3) + 8 * (lrow & 7);
    const int rsw = lrow & 3;
    const unsigned sm_b = su32(arena);

    // ---- compute mapping
    const int pc  = tid & 7;
    const int mg  = (tid >> 3) & 3;
    const int wid = tid >> 5;            // 0..7
    const int bg  = wid & 3;
    const int mgh = wid >> 2;            // 0/1: which half of each 8-row m-group
    int pcx[4];
    #pragma unroll
    for (int t = 0; t < 4; ++t) pcx[t] = 2 * ((pc >> 1) ^ t) + (pc & 1);
    const int xob = bg * 72;
    const int mob = mg * 72;
    int xidx[8], midx[4];
    #pragma unroll
    for (int i = 0; i < 8; ++i) xidx[i] = xob + 8 * i + pcx[i & 3];
    #pragma unroll
    for (int j = 0; j < 4; ++j) {
        const int jj = mgh * 4 + j;
        midx[j] = mob + 8 * jj + pcx[jj & 3];
    }
    // dden ownership: (mg, pc, wid) <-> (m-row mg*8+wid, pc): exact bijection
    const int dof = mob + 8 * wid + pcx[wid & 3];

    ull acc[8][4];
    ull dden = 0ull;
    #pragma unroll
    for (int i = 0; i < 8; ++i)
        #pragma unroll
        for (int j = 0; j < 4; ++j) acc[i][j] = 0ull;

#define LOAD_STAGE(buf, s)                                                        \
    {                                                                             \
        const size_t go = (size_t)(s) * CT * HWP;                                 \
        _Pragma("unroll")                                                         \
        for (int q = 0; q < 4; ++q) {                                             \
            const int df2 = rowb_f2 + 2 * (q ^ rsw);                              \
            unsigned d = sm_b + (unsigned)(((buf) * BUFF2 + df2) * 8);            \
            asm volatile("cp.async.cg.shared.global [%0], [%1], 16;"              \
                         ::"r"(d), "l"(lsrc + go + 4 * q));                       \
        }                                                                         \
        asm volatile("cp.async.commit_group;");                                   \
    }

#define STEP(cur, nxt, s)                                                         \
    {                                                                             \
        asm volatile("cp.async.wait_group 1;");                                   \
        __syncthreads();                                                          \
        {                                                                         \
            const int ns = ((s) + 2 < NSTEP) ? (s) + 2 : NSTEP - 1;               \
            LOAD_STAGE(nxt, ns);                                                  \
        }                                                                         \
        {                                                                         \
            const ull* xb = (const ull*)(arena + (cur) * BUFF2);                  \
            const ull* mb = xb + STAGEF2;                                         \
            _Pragma("unroll")                                                     \
            for (int c = 0; c < CT; ++c) {                                        \
                ull xr[8];                                                        \
                _Pragma("unroll")                                                 \
                for (int i = 0; i < 8; ++i) xr[i] = xb[c * CHF2 + xidx[i]];       \
                const ull dm = mb[c * CHF2 + dof];                                \
                asm("add.rn.f32x2 %0, %0, %1;" : "+l"(dden) : "l"(dm));           \
                _Pragma("unroll")                                                 \
                for (int j = 0; j < 4; ++j) {                                     \
                    const ull mr = mb[c * CHF2 + midx[j]];                        \
                    _Pragma("unroll")                                             \
                    for (int i = 0; i < 8; ++i)                                   \
                        asm("fma.rn.f32x2 %0, %1, %2, %0;"                        \
                            : "+l"(acc[i][j]) : "l"(xr[i]), "l"(mr));             \
                }                                                                 \
            }                                                                     \
        }                                                                         \
    }

    // ---- prologue
    LOAD_STAGE(0, 0)
    LOAD_STAGE(1, 1)

    // ---- main loop: 128 steps = 42*3 + 2
    for (int it = 0; it < 42; ++it) {
        const int s = it * 3;
        STEP(0, 2, s)
        STEP(1, 0, s + 1)
        STEP(2, 1, s + 2)
    }
    STEP(0, 2, 126)
    STEP(1, 0, 127)

    asm volatile("cp.async.wait_group 0;");
    __syncthreads();

    // ---- denominators -> sden
    *(ull*)&sden[(mg * 8 + wid) * 8 + pc] = dden;
    __syncthreads();

    // ---- fl = log(acc/den * 0.7 + 1e-10) -> fls overlay
    #pragma unroll
    for (int j = 0; j < 4; ++j) {
        const int mrow = mg * 8 + mgh * 4 + j;
        const float2 d = sden[mrow * 8 + pc];
        const float ivx = __fdividef(0.7f, fmaxf(d.x, 1e-12f));
        const float ivy = __fdividef(0.7f, fmaxf(d.y, 1e-12f));
        #pragma unroll
        for (int i = 0; i < 8; ++i) {
            const float2 a = *(const float2*)&acc[i][j];
            float2 f;
            f.x = __logf(a.x * ivx + 1e-10f);
            f.y = __logf(a.y * ivy + 1e-10f);
            fls[((bg * 8 + i) * 32 + mrow) * 8 + pc] = f;
        }
    }
    __syncthreads();

    // ---- occlusion-max + pixel reduction + global accumulate
    #pragma unroll
    for (int rep = 0; rep < 4; ++rep) {
        const int cell = tid + rep * 256;      // 0..1023
        const int b = cell >> 5;
        const int ml = cell & 31;
        const int m_g = mbase + ml;
        float2 fv[8];
        #pragma unroll
        for (int p = 0; p < 8; ++p) fv[p] = fls[cell * 8 + p];
        float sk[KK];
        #pragma unroll
        for (int k = 0; k < KK; ++k) {
            float s = 0.f;
            const float* bgp = g_bg + ((size_t)b * KK + k) * HWP + px0;
            #pragma unroll
            for (int pp = 0; pp < 4; ++pp) {
                const float4 bv = *(const float4*)(bgp + pp * 4);
                s += fmaxf(fv[2 * pp].x, bv.x) + fmaxf(fv[2 * pp].y, bv.y) +
                     fmaxf(fv[2 * pp + 1].x, bv.z) + fmaxf(fv[2 * pp + 1].y, bv.w);
            }
            sk[k] = s;
        }
        if (m_g < MM) {
            float* pmp = g_pm + ((size_t)b * MM + m_g) * KK;
            #pragma unroll
            for (int k = 0; k < KK; ++k) atomicAdd(&pmp[k], sk[k]);
        }
    }
#undef STEP
#undef LOAD_STAGE
}

// ---------------------------------------------------------------------------
__global__ void final_kernel(float* __restrict__ out) {
    const int idx = blockIdx.x * 256 + threadIdx.x;
    if (idx >= BB * NCC) return;
    const int b = idx / NCC, nc = idx % NCC;
    const float* p = g_pm + ((size_t)b * MM + nc * NMM) * KK;
    float m = -3.402823466e+38f;
    #pragma unroll
    for (int t = 0; t < NMM * KK; ++t) m = fmaxf(m, p[t]);
    out[idx] = m;
}

// ---------------------------------------------------------------------------
extern "C" void kernel_launch(void* const* d_in, const int* in_sizes, int n_in,
                              void* d_out, int out_size) {
    const float* x       = (const float*)d_in[0];
    const float* mix     = (const float*)d_in[1];
    const float* clutter = (const float*)d_in[2];
    float* out = (float*)d_out;

    const int fg_smem = ARENAF2 * 8;     // 67584 B
    cudaFuncSetAttribute(fg_kernel, cudaFuncAttributeMaxDynamicSharedMemorySize,
                         fg_smem);

    bg_kernel<<<dim3(49, BB), 256>>>(x, clutter);
    fg_kernel<<<dim3((MM + MT - 1) / MT, HWP / PT), 256, fg_smem>>>(x, mix);
    final_kernel<<<(BB * NCC + 255) / 256, 256>>>(out);
}

// round 10
// speedup vs baseline: 1.6943x; 1.6928x over previous
#include <cuda_runtime.h>
#include <cstdint>

#define BB 32
#define CC 512
#define HWP 784
#define MM 200
#define NCC 50
#define NMM 4
#define KK 5

#define MT 32
#define PT 16            // pixels per block tile (8 pairs)
#define CT 8             // channels per pipeline stage
#define NSTEP (CC / CT)  // 64

// smem layout (float2 units), per-channel layout identical to validated R5:
// per channel per operand: 4 groups of 8 rows, group stride 72 f2
// (8 rows x 8 f2 + 8 f2 pad); within each row the four 16B chunks are
// XOR-swizzled by (row&3). Two pipeline buffers (double buffer).
#define CHF2 288                   // 4 * 72
#define STAGEF2 (CT * CHF2)        // 2304 per operand
#define BUFF2 (2 * STAGEF2)        // x + m = 4608
#define SDENF2 (2 * BUFF2)         // 9216 (after both buffers; fls fits under)
#define ARENAF2 (SDENF2 + 256)     // 9472 f2 = 75776 B

typedef unsigned long long ull;

__device__ float g_bg[BB * KK * HWP];
__device__ float g_pm[BB * MM * KK];

__device__ __forceinline__ unsigned su32(const void* p) {
    return (unsigned)__cvta_generic_to_shared(p);
}

// ---------------------------------------------------------------------------
// bg (+ fused clutter normalization + g_pm zeroing)
// ---------------------------------------------------------------------------
__global__ void __launch_bounds__(256) bg_kernel(const float* __restrict__ x,
                                                 const float* __restrict__ clutter) {
    __shared__ float cls[KK * CC];
    __shared__ float part[16][16 * KK];
    __shared__ float red[8];
    __shared__ float rtot;

    const int tid = threadIdx.x;
    const int b = blockIdx.y;
    const int px0 = blockIdx.x * 16;
    const int lane = tid & 31, w = tid >> 5;

    const int zi = (blockIdx.y * 49 + blockIdx.x) * 256 + tid;
    if (zi < BB * MM * KK) g_pm[zi] = 0.0f;

    for (int k = 0; k < KK; ++k) {
        float v0 = fminf(fmaxf(clutter[k * CC + tid], 0.f), 1.f);
        float v1 = fminf(fmaxf(clutter[k * CC + 256 + tid], 0.f), 1.f);
        float s = v0 + v1;
        #pragma unroll
        for (int o = 16; o > 0; o >>= 1) s += __shfl_xor_sync(0xffffffffu, s, o);
        if (lane == 0) red[w] = s;
        __syncthreads();
        if (tid == 0) {
            float r = 0.f;
            #pragma unroll
            for (int q = 0; q < 8; ++q) r += red[q];
            rtot = fmaxf(r, 1e-12f);
        }
        __syncthreads();
        const float inv = __frcp_rn(rtot);
        cls[k * CC + tid] = v0 * inv;
        cls[k * CC + 256 + tid] = v1 * inv;
        __syncthreads();
    }

    const int px = tid & 15;
    const int cg = tid >> 4;
    float a0 = 0.f, a1 = 0.f, a2 = 0.f, a3 = 0.f, a4 = 0.f;
    const float* xb = x + ((size_t)b * CC + cg * 32) * HWP + px0 + px;
    #pragma unroll 4
    for (int ci = 0; ci < 32; ++ci) {
        const int c = cg * 32 + ci;
        const float xv = xb[(size_t)ci * HWP];
        a0 += xv * cls[0 * CC + c];
        a1 += xv * cls[1 * CC + c];
        a2 += xv * cls[2 * CC + c];
        a3 += xv * cls[3 * CC + c];
        a4 += xv * cls[4 * CC + c];
    }
    part[cg][px * KK + 0] = a0;
    part[cg][px * KK + 1] = a1;
    part[cg][px * KK + 2] = a2;
    part[cg][px * KK + 3] = a3;
    part[cg][px * KK + 4] = a4;
    __syncthreads();

    if (tid < 16 * KK) {
        float s = 0.f;
        #pragma unroll
        for (int g = 0; g < 16; ++g) s += part[g][tid];
        const int p = tid / KK, k = tid % KK;
        g_bg[((size_t)b * KK + k) * HWP + px0 + p] = __logf(s * 0.3f + 1e-10f);
    }
}

// ---------------------------------------------------------------------------
// fg: block 128 = 4bg(warps) x 4mg x 8pc ; thread tile 8b x 8m x 2px (1 pair).
// EXACT R5 structure (validated 345us) with CT=8 + double buffer: half the
// barrier/wait rounds, same layout / swizzle / lane mappings / registers.
// ---------------------------------------------------------------------------
__global__ void __launch_bounds__(128, 2) fg_kernel(const float* __restrict__ x,
                                                    const float* __restrict__ mix) {
    extern __shared__ float2 arena[];
    float2* sden = arena + SDENF2;       // [m(32)][pc(8)] float2
    float2* fls  = arena;                // epilogue overlay [b][m][pc]

    const int tid   = threadIdx.x;
    const int mtile = blockIdx.x;        // 7
    const int ptile = blockIdx.y;        // 49
    const int mbase = mtile * MT;
    const int px0   = ptile * PT;

    // ---- loader mapping: c_l = tid>>5 (channels c_l and c_l+4), r = tid&31
    const int c_l = tid >> 5;
    const int r   = tid & 31;
    const int mrow = (mbase + r < MM) ? mbase + r : MM - 1;
    const float* xsrc = x   + ((size_t)r    * CC + c_l) * HWP + px0;
    const float* msrc = mix + ((size_t)mrow * CC + c_l) * HWP + px0;
    const int rowb_f2 = c_l * CHF2 + 72 * (r >> 3) + 8 * (r & 7);
    const int rsw = r & 3;
    const unsigned sm_b = su32(arena);

    // ---- compute mapping (identical to R5)
    const int pc = tid & 7;
    const int mg = (tid >> 3) & 3;
    const int bg = tid >> 5;             // warp id
    int pcx[4];
    #pragma unroll
    for (int t = 0; t < 4; ++t) pcx[t] = 2 * ((pc >> 1) ^ t) + (pc & 1);
    const int xob = bg * 72;
    const int mob = mg * 72;
    const int dof = mob + 8 * bg + pcx[bg];   // dden rows j=bg and j=bg+4

    ull acc[8][8];
    ull dden[2] = {0ull, 0ull};
    #pragma unroll
    for (int i = 0; i < 8; ++i)
        #pragma unroll
        for (int j = 0; j < 8; ++j) acc[i][j] = 0ull;

#define LOAD_STAGE(buf, s)                                                        \
    {                                                                             \
        const size_t go = (size_t)(s) * CT * HWP;                                 \
        _Pragma("unroll")                                                         \
        for (int ch = 0; ch < 2; ++ch) {                                          \
            _Pragma("unroll")                                                     \
            for (int q = 0; q < 4; ++q) {                                         \
                const int df2 = rowb_f2 + ch * (4 * CHF2) + 2 * (q ^ rsw);        \
                unsigned dx = sm_b + (unsigned)(((buf) * BUFF2 + df2) * 8);       \
                unsigned dm = dx + (unsigned)(STAGEF2 * 8);                       \
                asm volatile("cp.async.cg.shared.global [%0], [%1], 16;"          \
                             ::"r"(dx), "l"(xsrc + go + ch * 4 * HWP + 4 * q));   \
                asm volatile("cp.async.cg.shared.global [%0], [%1], 16;"          \
                             ::"r"(dm), "l"(msrc + go + ch * 4 * HWP + 4 * q));   \
            }                                                                     \
        }                                                                         \
        asm volatile("cp.async.commit_group;");                                   \
    }

#define STEP(cur, nxt, s)                                                         \
    {                                                                             \
        asm volatile("cp.async.wait_group 0;");                                   \
        __syncthreads();                                                          \
        {                                                                         \
            const int ns = ((s) + 1 < NSTEP) ? (s) + 1 : NSTEP - 1;               \
            LOAD_STAGE(nxt, ns);                                                  \
        }                                                                         \
        {                                                                         \
            const ull* xb = (const ull*)(arena + (cur) * BUFF2);                  \
            const ull* mb = xb + STAGEF2;                                         \
            _Pragma("unroll")                                                     \
            for (int c = 0; c < CT; ++c) {                                        \
                ull xr[8];                                                        \
                _Pragma("unroll")                                                 \
                for (int i = 0; i < 8; ++i)                                       \
                    xr[i] = xb[c * CHF2 + xob + 8 * i + pcx[i & 3]];              \
                const ull d0 = mb[c * CHF2 + dof];                                \
                const ull d1 = mb[c * CHF2 + dof + 32];                           \
                asm("add.rn.f32x2 %0, %0, %1;" : "+l"(dden[0]) : "l"(d0));        \
                asm("add.rn.f32x2 %0, %0, %1;" : "+l"(dden[1]) : "l"(d1));        \
                _Pragma("unroll")                                                 \
                for (int j = 0; j < 8; ++j) {                                     \
                    const ull mr = mb[c * CHF2 + mob + 8 * j + pcx[j & 3]];       \
                    _Pragma("unroll")                                             \
                    for (int i = 0; i < 8; ++i)                                   \
                        asm("fma.rn.f32x2 %0, %1, %2, %0;"                        \
                            : "+l"(acc[i][j]) : "l"(xr[i]), "l"(mr));             \
                }                                                                 \
            }                                                                     \
        }                                                                         \
    }

    // ---- prologue: stage 0 -> buffer 0
    LOAD_STAGE(0, 0)

    // ---- main loop: 64 steps, unrolled x2 for static buffer indices
    for (int it = 0; it < 32; ++it) {
        const int s = it * 2;
        STEP(0, 1, s)
        STEP(1, 0, s + 1)
    }

    asm volatile("cp.async.wait_group 0;");
    __syncthreads();

    // ---- denominators -> sden (each warp owns m-rows j=bg, bg+4 per mg)
    *(ull*)&sden[(mg * 8 + bg) * 8 + pc] = dden[0];
    *(ull*)&sden[(mg * 8 + bg + 4) * 8 + pc] = dden[1];
    __syncthreads();

    // ---- fl = log(acc/den * 0.7 + 1e-10) -> fls overlay
    #pragma unroll
    for (int j = 0; j < 8; ++j) {
        const float2 d = sden[(mg * 8 + j) * 8 + pc];
        const float ivx = __fdividef(0.7f, fmaxf(d.x, 1e-12f));
        const float ivy = __fdividef(0.7f, fmaxf(d.y, 1e-12f));
        #pragma unroll
        for (int i = 0; i < 8; ++i) {
            const float2 a = *(const float2*)&acc[i][j];
            float2 f;
            f.x = __logf(a.x * ivx + 1e-10f);
            f.y = __logf(a.y * ivy + 1e-10f);
            fls[((bg * 8 + i) * 32 + (mg * 8 + j)) * 8 + pc] = f;
        }
    }
    __syncthreads();

    // ---- occlusion-max + pixel reduction + global accumulate
    #pragma unroll
    for (int rep = 0; rep < 8; ++rep) {
        const int cell = tid + rep * 128;      // 0..1023
        const int b = cell >> 5;
        const int ml = cell & 31;
        const int m_g = mbase + ml;
        float2 fv[8];
        #pragma unroll
        for (int p = 0; p < 8; ++p) fv[p] = fls[cell * 8 + p];
        float sk[KK];
        #pragma unroll
        for (int k = 0; k < KK; ++k) {
            float s = 0.f;
            const float* bgp = g_bg + ((size_t)b * KK + k) * HWP + px0;
            #pragma unroll
            for (int pp = 0; pp < 4; ++pp) {
                const float4 bv = *(const float4*)(bgp + pp * 4);
                s += fmaxf(fv[2 * pp].x, bv.x) + fmaxf(fv[2 * pp].y, bv.y) +
                     fmaxf(fv[2 * pp + 1].x, bv.z) + fmaxf(fv[2 * pp + 1].y, bv.w);
            }
            sk[k] = s;
        }
        if (m_g < MM) {
            float* pmp = g_pm + ((size_t)b * MM + m_g) * KK;
            #pragma unroll
            for (int k = 0; k < KK; ++k) atomicAdd(&pmp[k], sk[k]);
        }
    }
#undef STEP
#undef LOAD_STAGE
}

// ---------------------------------------------------------------------------
__global__ void final_kernel(float* __restrict__ out) {
    const int idx = blockIdx.x * 256 + threadIdx.x;
    if (idx >= BB * NCC) return;
    const int b = idx / NCC, nc = idx % NCC;
    const float* p = g_pm + ((size_t)b * MM + nc * NMM) * KK;
    float m = -3.402823466e+38f;
    #pragma unroll
    for (int t = 0; t < NMM * KK; ++t) m = fmaxf(m, p[t]);
    out[idx] = m;
}

// ---------------------------------------------------------------------------
extern "C" void kernel_launch(void* const* d_in, const int* in_sizes, int n_in,
                              void* d_out, int out_size) {
    const float* x       = (const float*)d_in[0];
    const float* mix     = (const float*)d_in[1];
    const float* clutter = (const float*)d_in[2];
    float* out = (float*)d_out;

    const int fg_smem = ARENAF2 * 8;     // 75776 B
    cudaFuncSetAttribute(fg_kernel, cudaFuncAttributeMaxDynamicSharedMemorySize,
                         fg_smem);

    bg_kernel<<<dim3(49, BB), 256>>>(x, clutter);
    fg_kernel<<<dim3((MM + MT - 1) / MT, HWP / PT), 128, fg_smem>>>(x, mix);
    final_kernel<<<(BB * NCC + 255) / 256, 256>>>(out);
}